// round 1
// baseline (speedup 1.0000x reference)
#include <cuda_runtime.h>
#include <cuda_bf16.h>
#include <cstdint>

// Problem constants (fixed by the reference)
#define N_NODES 50000
#define N_EDGES 800000
#define D 64          // D_IN == D_OUT == 64
#define D2 128        // concat dim

// Scratch: aggregation buffers (allowed as __device__ globals; no allocs)
__device__ float g_hsum[N_NODES * D];   // 12.8 MB
__device__ float g_deg[N_NODES];        // 200 KB

// ---------------------------------------------------------------------------
// Kernel 1: zero the scratch
// ---------------------------------------------------------------------------
__global__ void zero_scratch_kernel() {
    int idx = blockIdx.x * blockDim.x + threadIdx.x;
    int total = N_NODES * D;
    // vectorized zero of g_hsum
    float4* p = reinterpret_cast<float4*>(g_hsum);
    for (int i = idx; i < total / 4; i += gridDim.x * blockDim.x) {
        p[i] = make_float4(0.f, 0.f, 0.f, 0.f);
    }
    for (int i = idx; i < N_NODES; i += gridDim.x * blockDim.x) {
        g_deg[i] = 0.f;
    }
}

// ---------------------------------------------------------------------------
// Kernel 2: edge scatter. One thread per (edge, 4-feature chunk).
// 16 chunks of float4 cover D=64. h row gathers are L2-resident (12.8MB).
// ---------------------------------------------------------------------------
__global__ void scatter_kernel(const float* __restrict__ h,
                               const float* __restrict__ w,
                               const int*   __restrict__ src,
                               const int*   __restrict__ dst) {
    int t = blockIdx.x * blockDim.x + threadIdx.x;
    const int CHUNKS = D / 4;                 // 16
    if (t >= N_EDGES * CHUNKS) return;
    int e = t >> 4;          // t / 16
    int c = t & 15;          // t % 16

    int s  = src[e];
    int dd = dst[e];
    float we = w[e];

    const float4* hrow = reinterpret_cast<const float4*>(h + (size_t)s * D);
    float4 hv = hrow[c];

    float* out = g_hsum + (size_t)dd * D + c * 4;
    atomicAdd(out + 0, hv.x * we);
    atomicAdd(out + 1, hv.y * we);
    atomicAdd(out + 2, hv.z * we);
    atomicAdd(out + 3, hv.w * we);

    if (c == 0) {
        atomicAdd(&g_deg[dd], 1.0f);
    }
}

// ---------------------------------------------------------------------------
// Kernel 3: normalize + concat + linear.
// Block = 256 threads = 8 warps = 8 nodes. W (64x128) is staged transposed in
// shared as Ws[k*64 + o] so a warp reading o = lane / lane+32 at fixed k is
// conflict-free; h_total row staged per-warp in shared for broadcast reads.
// out[n][o] = b[o] + sum_k hT[n][k] * W[o][k]
// ---------------------------------------------------------------------------
__global__ __launch_bounds__(256, 4)
void linear_kernel(const float* __restrict__ h,
                   const float* __restrict__ W,     // [64, 128] row-major
                   const float* __restrict__ b,     // [64]
                   float* __restrict__ out) {       // [N, 64]
    __shared__ float Ws[D2 * D];      // 32 KB, transposed: Ws[k*64+o] = W[o*128+k]
    __shared__ float bsh[D];
    __shared__ float hsh[8][D2];      // per-warp concat row

    int tid = threadIdx.x;
    // stage W transposed
    for (int i = tid; i < D2 * D; i += 256) {
        int o = i / D2;
        int k = i % D2;
        Ws[k * D + o] = W[i];
    }
    if (tid < D) bsh[tid] = b[tid];
    __syncthreads();

    int warp = tid >> 5;
    int lane = tid & 31;
    int n = blockIdx.x * 8 + warp;
    if (n >= N_NODES) return;

    // build concat row: [h[n] (64), h_N[n] (64)]
    float dv = g_deg[n];
    float inv = 1.0f / fmaxf(dv, 1.0f);
    hsh[warp][lane]       = h[(size_t)n * D + lane];
    hsh[warp][lane + 32]  = h[(size_t)n * D + lane + 32];
    hsh[warp][64 + lane]      = g_hsum[(size_t)n * D + lane] * inv;
    hsh[warp][64 + lane + 32] = g_hsum[(size_t)n * D + lane + 32] * inv;
    __syncwarp();

    int o0 = lane;
    int o1 = lane + 32;
    float acc0 = bsh[o0];
    float acc1 = bsh[o1];
    const float* hrow = hsh[warp];

    #pragma unroll
    for (int k = 0; k < D2; k++) {
        float hv = hrow[k];               // broadcast LDS
        acc0 += hv * Ws[k * D + o0];
        acc1 += hv * Ws[k * D + o1];
    }

    out[(size_t)n * D + o0] = acc0;
    out[(size_t)n * D + o1] = acc1;
}

// ---------------------------------------------------------------------------
// Launch
// ---------------------------------------------------------------------------
extern "C" void kernel_launch(void* const* d_in, const int* in_sizes, int n_in,
                              void* d_out, int out_size) {
    const float* h   = (const float*)d_in[0];   // [50000, 64]
    const float* w   = (const float*)d_in[1];   // [800000]
    const int*   src = (const int*)  d_in[2];   // [800000]
    const int*   dst = (const int*)  d_in[3];   // [800000]
    const float* W   = (const float*)d_in[4];   // [64, 128]
    const float* b   = (const float*)d_in[5];   // [64]
    float* out = (float*)d_out;                 // [50000, 64]

    (void)in_sizes; (void)n_in; (void)out_size;

    // 1. zero scratch
    zero_scratch_kernel<<<592, 256>>>();

    // 2. edge scatter (one thread per edge x float4 chunk)
    int scatter_threads = N_EDGES * (D / 4);        // 12.8M
    int scatter_blocks = (scatter_threads + 255) / 256;
    scatter_kernel<<<scatter_blocks, 256>>>(h, w, src, dst);

    // 3. normalize + concat + linear
    int lin_blocks = (N_NODES + 7) / 8;
    linear_kernel<<<lin_blocks, 256>>>(h, W, b, out);
}

// round 2
// speedup vs baseline: 1.0782x; 1.0782x over previous
#include <cuda_runtime.h>
#include <cuda_bf16.h>
#include <cstdint>

// Problem constants (fixed by the reference)
#define N_NODES 50000
#define N_EDGES 800000
#define D 64          // D_IN == D_OUT == 64
#define D2 128        // concat dim

// ---------------------------------------------------------------------------
// Scratch (__device__ globals; no allocations anywhere)
// ---------------------------------------------------------------------------
struct __align__(8) EdgeRec { int s; float w; };

__device__ float   g_hsum[N_NODES * D];   // 12.8 MB aggregated messages
__device__ int     g_count[N_NODES];      // in-degree per node
__device__ int     g_start[N_NODES];      // CSR row offsets (by dst)
__device__ int     g_cursor[N_NODES];     // atomic fill cursors
__device__ EdgeRec g_edge[N_EDGES];       // packed {src, w} per CSR slot

// ---------------------------------------------------------------------------
// K1: zero the degree counters
// ---------------------------------------------------------------------------
__global__ void zero_count_kernel() {
    int i = blockIdx.x * blockDim.x + threadIdx.x;
    if (i < N_NODES) g_count[i] = 0;
}

// ---------------------------------------------------------------------------
// K2: histogram of dst -> degree counts (int atomics, spread addresses)
// ---------------------------------------------------------------------------
__global__ void hist_kernel(const int* __restrict__ dst) {
    int e = blockIdx.x * blockDim.x + threadIdx.x;
    if (e >= N_EDGES) return;
    atomicAdd(&g_count[dst[e]], 1);
}

// ---------------------------------------------------------------------------
// K3: single-block exclusive scan of g_count -> g_start (and init g_cursor).
// 1024 threads x 49 elements = 50176 >= 50000.
// ---------------------------------------------------------------------------
__global__ __launch_bounds__(1024) void scan_kernel() {
    __shared__ int sh[1024];
    const int PER = 49;
    int t = threadIdx.x;
    int base = t * PER;

    int local[PER];
    int sum = 0;
    #pragma unroll
    for (int i = 0; i < PER; i++) {
        int idx = base + i;
        int c = (idx < N_NODES) ? g_count[idx] : 0;
        local[i] = sum;       // exclusive within-thread prefix
        sum += c;
    }
    sh[t] = sum;
    __syncthreads();

    // inclusive Hillis-Steele scan over 1024 thread totals
    for (int d2 = 1; d2 < 1024; d2 <<= 1) {
        int add = (t >= d2) ? sh[t - d2] : 0;
        __syncthreads();
        sh[t] += add;
        __syncthreads();
    }
    int excl = sh[t] - sum;   // exclusive prefix of this thread's range

    #pragma unroll
    for (int i = 0; i < PER; i++) {
        int idx = base + i;
        if (idx < N_NODES) {
            int v = excl + local[i];
            g_start[idx]  = v;
            g_cursor[idx] = v;
        }
    }
}

// ---------------------------------------------------------------------------
// K4: position scatter — claim a CSR slot per edge, store packed {src, w}.
// ---------------------------------------------------------------------------
__global__ void pos_kernel(const int* __restrict__ src,
                           const int* __restrict__ dst,
                           const float* __restrict__ w) {
    int e = blockIdx.x * blockDim.x + threadIdx.x;
    if (e >= N_EDGES) return;
    int d = dst[e];
    int p = atomicAdd(&g_cursor[d], 1);
    EdgeRec r;
    r.s = src[e];
    r.w = w[e];
    g_edge[p] = r;
}

// ---------------------------------------------------------------------------
// K5: warp-per-node gather. Each lane owns 2 features (float2).
// Per edge: 1 uniform LDG.64 (edge rec) + 1 coalesced LDG.64/lane (h row,
// L2-resident). Unroll x2 for MLP. Single store per node row -> no zero-init
// of g_hsum needed.
// ---------------------------------------------------------------------------
__global__ __launch_bounds__(256) void gather_kernel(const float* __restrict__ h) {
    int warp = threadIdx.x >> 5;
    int lane = threadIdx.x & 31;
    int n = blockIdx.x * 8 + warp;
    if (n >= N_NODES) return;

    int beg = g_start[n];
    int cnt = g_count[n];

    const float2* __restrict__ h2 = reinterpret_cast<const float2*>(h);
    float ax = 0.f, ay = 0.f;

    int j = 0;
    for (; j + 1 < cnt; j += 2) {
        EdgeRec e0 = g_edge[beg + j];
        EdgeRec e1 = g_edge[beg + j + 1];
        float2 h0 = h2[(size_t)e0.s * 32 + lane];
        float2 h1 = h2[(size_t)e1.s * 32 + lane];
        ax += h0.x * e0.w;
        ay += h0.y * e0.w;
        ax += h1.x * e1.w;
        ay += h1.y * e1.w;
    }
    if (j < cnt) {
        EdgeRec e0 = g_edge[beg + j];
        float2 h0 = h2[(size_t)e0.s * 32 + lane];
        ax += h0.x * e0.w;
        ay += h0.y * e0.w;
    }

    reinterpret_cast<float2*>(g_hsum)[(size_t)n * 32 + lane] = make_float2(ax, ay);
}

// ---------------------------------------------------------------------------
// K6: normalize + concat + linear (unchanged structure; deg from g_count).
// out[n][o] = b[o] + sum_k hT[n][k] * W[o][k]
// ---------------------------------------------------------------------------
__global__ __launch_bounds__(256, 4)
void linear_kernel(const float* __restrict__ h,
                   const float* __restrict__ W,     // [64, 128] row-major
                   const float* __restrict__ b,     // [64]
                   float* __restrict__ out) {       // [N, 64]
    __shared__ float Ws[D2 * D];      // 32 KB, transposed: Ws[k*64+o] = W[o*128+k]
    __shared__ float bsh[D];
    __shared__ float hsh[8][D2];      // per-warp concat row

    int tid = threadIdx.x;
    for (int i = tid; i < D2 * D; i += 256) {
        int o = i / D2;
        int k = i % D2;
        Ws[k * D + o] = W[i];
    }
    if (tid < D) bsh[tid] = b[tid];
    __syncthreads();

    int warp = tid >> 5;
    int lane = tid & 31;
    int n = blockIdx.x * 8 + warp;
    if (n >= N_NODES) return;

    float inv = 1.0f / fmaxf((float)g_count[n], 1.0f);
    hsh[warp][lane]           = h[(size_t)n * D + lane];
    hsh[warp][lane + 32]      = h[(size_t)n * D + lane + 32];
    hsh[warp][64 + lane]      = g_hsum[(size_t)n * D + lane] * inv;
    hsh[warp][64 + lane + 32] = g_hsum[(size_t)n * D + lane + 32] * inv;
    __syncwarp();

    int o0 = lane;
    int o1 = lane + 32;
    float acc0 = bsh[o0];
    float acc1 = bsh[o1];
    const float* hrow = hsh[warp];

    #pragma unroll
    for (int k = 0; k < D2; k++) {
        float hv = hrow[k];
        acc0 += hv * Ws[k * D + o0];
        acc1 += hv * Ws[k * D + o1];
    }

    out[(size_t)n * D + o0] = acc0;
    out[(size_t)n * D + o1] = acc1;
}

// ---------------------------------------------------------------------------
// Launch
// ---------------------------------------------------------------------------
extern "C" void kernel_launch(void* const* d_in, const int* in_sizes, int n_in,
                              void* d_out, int out_size) {
    const float* h   = (const float*)d_in[0];   // [50000, 64]
    const float* w   = (const float*)d_in[1];   // [800000]
    const int*   src = (const int*)  d_in[2];   // [800000]
    const int*   dst = (const int*)  d_in[3];   // [800000]
    const float* W   = (const float*)d_in[4];   // [64, 128]
    const float* b   = (const float*)d_in[5];   // [64]
    float* out = (float*)d_out;                 // [50000, 64]

    (void)in_sizes; (void)n_in; (void)out_size;

    zero_count_kernel<<<(N_NODES + 255) / 256, 256>>>();
    hist_kernel<<<(N_EDGES + 255) / 256, 256>>>(dst);
    scan_kernel<<<1, 1024>>>();
    pos_kernel<<<(N_EDGES + 255) / 256, 256>>>(src, dst, w);
    gather_kernel<<<(N_NODES + 7) / 8, 256>>>(h);
    linear_kernel<<<(N_NODES + 7) / 8, 256>>>(h, W, b, out);
}

// round 3
// speedup vs baseline: 3.7765x; 3.5025x over previous
#include <cuda_runtime.h>
#include <cuda_bf16.h>
#include <cstdint>

#define N_NODES 50000
#define N_EDGES 800000
#define D 64
#define D2 128

#define SCAN_BLK 1024
#define NBLK_SCAN 49          // ceil(50000/1024)

#define WPB 6                 // warps per block in fused kernel
#define TPB (WPB * 32)        // 192 threads
#define GPW 4                 // nodes per warp per iteration

// ---------------------------------------------------------------------------
// Scratch (__device__ globals; no allocations anywhere)
// ---------------------------------------------------------------------------
struct __align__(8) EdgeRec { int s; float w; };

__device__ int     g_count[N_NODES];
__device__ int     g_start[N_NODES];
__device__ int     g_cursor[N_NODES];
__device__ int     g_bsum[NBLK_SCAN];
__device__ int     g_boff[NBLK_SCAN];
__device__ EdgeRec g_edge[N_EDGES];

// ---------------------------------------------------------------------------
// K1: zero degree counters
// ---------------------------------------------------------------------------
__global__ void zero_count_kernel() {
    int i = blockIdx.x * blockDim.x + threadIdx.x;
    if (i < N_NODES) g_count[i] = 0;
}

// ---------------------------------------------------------------------------
// K2: histogram dst -> in-degree (int atomics, 50k spread addresses)
// ---------------------------------------------------------------------------
__global__ void hist_kernel(const int* __restrict__ dst) {
    int e = blockIdx.x * blockDim.x + threadIdx.x;
    if (e >= N_EDGES) return;
    atomicAdd(&g_count[dst[e]], 1);
}

// ---------------------------------------------------------------------------
// K3a: per-block (1024-elem) exclusive scan, coalesced. Writes within-block
// exclusive prefix to g_start and block total to g_bsum.
// ---------------------------------------------------------------------------
__global__ __launch_bounds__(SCAN_BLK) void scanA_kernel() {
    __shared__ int sh[SCAN_BLK];
    int t = threadIdx.x;
    int i = blockIdx.x * SCAN_BLK + t;
    int c = (i < N_NODES) ? g_count[i] : 0;
    sh[t] = c;
    __syncthreads();
    for (int d = 1; d < SCAN_BLK; d <<= 1) {
        int v = (t >= d) ? sh[t - d] : 0;
        __syncthreads();
        sh[t] += v;
        __syncthreads();
    }
    if (i < N_NODES) g_start[i] = sh[t] - c;   // exclusive within block
    if (t == SCAN_BLK - 1) g_bsum[blockIdx.x] = sh[t];
}

// ---------------------------------------------------------------------------
// K3b: scan the 49 block sums (single block of 64 threads)
// ---------------------------------------------------------------------------
__global__ void scanB_kernel() {
    __shared__ int sh[64];
    int t = threadIdx.x;
    int c = (t < NBLK_SCAN) ? g_bsum[t] : 0;
    sh[t] = c;
    __syncthreads();
    for (int d = 1; d < 64; d <<= 1) {
        int v = (t >= d) ? sh[t - d] : 0;
        __syncthreads();
        sh[t] += v;
        __syncthreads();
    }
    if (t < NBLK_SCAN) g_boff[t] = sh[t] - c;  // exclusive
}

// ---------------------------------------------------------------------------
// K3c: add block offsets; init fill cursors
// ---------------------------------------------------------------------------
__global__ void scanC_kernel() {
    int i = blockIdx.x * blockDim.x + threadIdx.x;
    if (i >= N_NODES) return;
    int v = g_start[i] + g_boff[i >> 10];
    g_start[i]  = v;
    g_cursor[i] = v;
}

// ---------------------------------------------------------------------------
// K4: position scatter — claim CSR slot, store packed {src, w}
// ---------------------------------------------------------------------------
__global__ void pos_kernel(const int* __restrict__ src,
                           const int* __restrict__ dst,
                           const float* __restrict__ w) {
    int e = blockIdx.x * blockDim.x + threadIdx.x;
    if (e >= N_EDGES) return;
    int d = dst[e];
    int p = atomicAdd(&g_cursor[d], 1);
    EdgeRec r;
    r.s = src[e];
    r.w = w[e];
    g_edge[p] = r;
}

// ---------------------------------------------------------------------------
// K5: FUSED gather + normalize + concat + linear.
// Warp handles GPW=4 nodes per iteration:
//   phase A: gather h_N rows (lane owns feats 2*lane, 2*lane+1), build concat
//            rows in smem (hsh), 128 floats per node.
//   phase B: matvec. W staged once per block as float2 Wp[k*33+o] =
//            {W[o][k], W[o+32][k]}, pad 33 -> conflict-free LDS.64.
//            Per 4-k chunk: 4x LDS.64 (W, shared by 4 nodes) +
//            4x LDS.128 broadcast (h rows) + 32 FFMA.
// smem: Wp 33.0KB + hsh 12KB = 46KB < 48KB static limit.
// ---------------------------------------------------------------------------
__global__ __launch_bounds__(TPB)
void fused_kernel(const float* __restrict__ h,
                  const float* __restrict__ W,   // [64, 128] row-major
                  const float* __restrict__ b,   // [64]
                  float* __restrict__ out) {     // [N, 64]
    __shared__ float2 Wp[D2 * 33];               // Wp[k*33+o], o in 0..31
    __shared__ float4 hsh4[WPB][GPW][D2 / 4];    // concat rows, float4 view

    int tid = threadIdx.x;
    // stage W: conflict-free STS (lane -> consecutive o)
    for (int i = tid; i < D2 * 32; i += TPB) {
        int k = i >> 5;
        int o = i & 31;
        Wp[k * 33 + o] = make_float2(W[o * D2 + k], W[(o + 32) * D2 + k]);
    }
    __syncthreads();

    int warp = tid >> 5;
    int lane = tid & 31;
    float b0 = b[lane];
    float b1 = b[lane + 32];
    const float2* __restrict__ h2 = reinterpret_cast<const float2*>(h);

    int gw = blockIdx.x * WPB + warp;
    int nwarps = gridDim.x * WPB;
    const int ngroups = (N_NODES + GPW - 1) / GPW;   // 12500

    for (int g = gw; g < ngroups; g += nwarps) {
        int n0 = g * GPW;

        // ---- phase A: gather ----
        #pragma unroll
        for (int u = 0; u < GPW; u++) {
            int n = n0 + u;
            if (n >= N_NODES) break;
            int beg = g_start[n];
            int cnt = g_count[n];
            float ax = 0.f, ay = 0.f;
            int j = 0;
            for (; j + 1 < cnt; j += 2) {
                EdgeRec e0 = g_edge[beg + j];
                EdgeRec e1 = g_edge[beg + j + 1];
                float2 h0 = h2[(size_t)e0.s * 32 + lane];
                float2 h1 = h2[(size_t)e1.s * 32 + lane];
                ax += h0.x * e0.w + h1.x * e1.w;
                ay += h0.y * e0.w + h1.y * e1.w;
            }
            if (j < cnt) {
                EdgeRec e0 = g_edge[beg + j];
                float2 h0 = h2[(size_t)e0.s * 32 + lane];
                ax += h0.x * e0.w;
                ay += h0.y * e0.w;
            }
            float inv = 1.0f / fmaxf((float)cnt, 1.0f);
            float2* row2 = reinterpret_cast<float2*>(&hsh4[warp][u][0]);
            row2[lane]      = h2[(size_t)n * 32 + lane];          // h part
            row2[32 + lane] = make_float2(ax * inv, ay * inv);    // h_N part
        }
        __syncwarp();

        // ---- phase B: matvec ----
        float acc0[GPW], acc1[GPW];
        #pragma unroll
        for (int u = 0; u < GPW; u++) { acc0[u] = b0; acc1[u] = b1; }

        #pragma unroll 4
        for (int kq = 0; kq < D2 / 4; kq++) {
            float2 w0 = Wp[(4 * kq + 0) * 33 + lane];
            float2 w1 = Wp[(4 * kq + 1) * 33 + lane];
            float2 w2 = Wp[(4 * kq + 2) * 33 + lane];
            float2 w3 = Wp[(4 * kq + 3) * 33 + lane];
            #pragma unroll
            for (int u = 0; u < GPW; u++) {
                float4 hv = hsh4[warp][u][kq];   // broadcast LDS.128
                acc0[u] += hv.x * w0.x + hv.y * w1.x + hv.z * w2.x + hv.w * w3.x;
                acc1[u] += hv.x * w0.y + hv.y * w1.y + hv.z * w2.y + hv.w * w3.y;
            }
        }

        #pragma unroll
        for (int u = 0; u < GPW; u++) {
            int n = n0 + u;
            if (n >= N_NODES) break;
            out[(size_t)n * D + lane]      = acc0[u];
            out[(size_t)n * D + lane + 32] = acc1[u];
        }
        __syncwarp();   // protect hsh before next iteration overwrites
    }
}

// ---------------------------------------------------------------------------
// Launch
// ---------------------------------------------------------------------------
extern "C" void kernel_launch(void* const* d_in, const int* in_sizes, int n_in,
                              void* d_out, int out_size) {
    const float* h   = (const float*)d_in[0];   // [50000, 64]
    const float* w   = (const float*)d_in[1];   // [800000]
    const int*   src = (const int*)  d_in[2];   // [800000]
    const int*   dst = (const int*)  d_in[3];   // [800000]
    const float* W   = (const float*)d_in[4];   // [64, 128]
    const float* b   = (const float*)d_in[5];   // [64]
    float* out = (float*)d_out;                 // [50000, 64]

    (void)in_sizes; (void)n_in; (void)out_size;

    zero_count_kernel<<<(N_NODES + 255) / 256, 256>>>();
    hist_kernel<<<(N_EDGES + 255) / 256, 256>>>(dst);
    scanA_kernel<<<NBLK_SCAN, SCAN_BLK>>>();
    scanB_kernel<<<1, 64>>>();
    scanC_kernel<<<(N_NODES + 255) / 256, 256>>>();
    pos_kernel<<<(N_EDGES + 255) / 256, 256>>>(src, dst, w);
    fused_kernel<<<592, TPB>>>(h, W, b, out);
}

// round 4
// speedup vs baseline: 3.8009x; 1.0064x over previous
#include <cuda_runtime.h>
#include <cuda_bf16.h>
#include <cstdint>

#define N_NODES 50000
#define N_EDGES 800000
#define D 64
#define D2 128

#define SCAN_BLK 1024
#define NBLK_SCAN 49          // ceil(50000/1024)

#define WPB 6                 // warps per block in fused kernel
#define TPB (WPB * 32)        // 192 threads
#define GPW 4                 // nodes per warp per iteration

// ---------------------------------------------------------------------------
// Scratch (__device__ globals; no allocations anywhere)
// ---------------------------------------------------------------------------
struct __align__(8) EdgeRec { int s; float w; };

__device__ int     g_count[N_NODES];
__device__ int     g_start[N_NODES];
__device__ int     g_cursor[N_NODES];
__device__ int     g_bsum[NBLK_SCAN];
__device__ EdgeRec g_edge[N_EDGES];

// ---------------------------------------------------------------------------
// K1: zero degree counters
// ---------------------------------------------------------------------------
__global__ void zero_count_kernel() {
    int i = blockIdx.x * blockDim.x + threadIdx.x;
    if (i < N_NODES) g_count[i] = 0;
}

// ---------------------------------------------------------------------------
// K2: histogram dst -> in-degree. 4 edges/thread, vectorized loads ->
// 4 independent REDs in flight (latency-bound before; issue 4%).
// N_EDGES % 4 == 0.
// ---------------------------------------------------------------------------
__global__ void hist_kernel(const int* __restrict__ dst) {
    int t = blockIdx.x * blockDim.x + threadIdx.x;
    if (t >= N_EDGES / 4) return;
    int4 d4 = reinterpret_cast<const int4*>(dst)[t];
    atomicAdd(&g_count[d4.x], 1);
    atomicAdd(&g_count[d4.y], 1);
    atomicAdd(&g_count[d4.z], 1);
    atomicAdd(&g_count[d4.w], 1);
}

// ---------------------------------------------------------------------------
// K3a: per-block (1024-elem) exclusive scan, coalesced.
// ---------------------------------------------------------------------------
__global__ __launch_bounds__(SCAN_BLK) void scanA_kernel() {
    __shared__ int sh[SCAN_BLK];
    int t = threadIdx.x;
    int i = blockIdx.x * SCAN_BLK + t;
    int c = (i < N_NODES) ? g_count[i] : 0;
    sh[t] = c;
    __syncthreads();
    for (int d = 1; d < SCAN_BLK; d <<= 1) {
        int v = (t >= d) ? sh[t - d] : 0;
        __syncthreads();
        sh[t] += v;
        __syncthreads();
    }
    if (i < N_NODES) g_start[i] = sh[t] - c;   // exclusive within block
    if (t == SCAN_BLK - 1) g_bsum[blockIdx.x] = sh[t];
}

// ---------------------------------------------------------------------------
// K3b: add block offsets + init cursors. Each 256-thread block covers 256
// nodes = exactly one 1024-group slice, so the needed offset is a single
// prefix sum of g_bsum[0..g-1]; thread 0 computes it (<=48 adds, L2-hit),
// broadcasts via smem. (Replaces the separate scanB launch.)
// ---------------------------------------------------------------------------
__global__ void scanC_kernel() {
    __shared__ int off_sh;
    int i = blockIdx.x * blockDim.x + threadIdx.x;
    int grp = (blockIdx.x * blockDim.x) >> 10;   // same for whole block
    if (threadIdx.x == 0) {
        int s = 0;
        for (int j = 0; j < grp; j++) s += g_bsum[j];
        off_sh = s;
    }
    __syncthreads();
    if (i >= N_NODES) return;
    int v = g_start[i] + off_sh;
    g_start[i]  = v;
    g_cursor[i] = v;
}

// ---------------------------------------------------------------------------
// K4: position scatter — 4 edges/thread, vectorized loads, 4 independent
// ATOMG in flight per thread (ATOMG lat 318; was issue-starved at 1/thread).
// ---------------------------------------------------------------------------
__global__ void pos_kernel(const int* __restrict__ src,
                           const int* __restrict__ dst,
                           const float* __restrict__ w) {
    int t = blockIdx.x * blockDim.x + threadIdx.x;
    if (t >= N_EDGES / 4) return;
    int4   s4 = reinterpret_cast<const int4*>(src)[t];
    int4   d4 = reinterpret_cast<const int4*>(dst)[t];
    float4 w4 = reinterpret_cast<const float4*>(w)[t];

    int p0 = atomicAdd(&g_cursor[d4.x], 1);
    int p1 = atomicAdd(&g_cursor[d4.y], 1);
    int p2 = atomicAdd(&g_cursor[d4.z], 1);
    int p3 = atomicAdd(&g_cursor[d4.w], 1);

    EdgeRec r;
    r.s = s4.x; r.w = w4.x; g_edge[p0] = r;
    r.s = s4.y; r.w = w4.y; g_edge[p1] = r;
    r.s = s4.z; r.w = w4.z; g_edge[p2] = r;
    r.s = s4.w; r.w = w4.w; g_edge[p3] = r;
}

// ---------------------------------------------------------------------------
// K5: FUSED gather + normalize + concat + linear. (Structure as R3; gather
// unrolled x4 for deeper MLP against L2 latency.)
// ---------------------------------------------------------------------------
__global__ __launch_bounds__(TPB)
void fused_kernel(const float* __restrict__ h,
                  const float* __restrict__ W,   // [64, 128] row-major
                  const float* __restrict__ b,   // [64]
                  float* __restrict__ out) {     // [N, 64]
    __shared__ float2 Wp[D2 * 33];               // Wp[k*33+o], o in 0..31
    __shared__ float4 hsh4[WPB][GPW][D2 / 4];    // concat rows, float4 view

    int tid = threadIdx.x;
    for (int i = tid; i < D2 * 32; i += TPB) {
        int k = i >> 5;
        int o = i & 31;
        Wp[k * 33 + o] = make_float2(W[o * D2 + k], W[(o + 32) * D2 + k]);
    }
    __syncthreads();

    int warp = tid >> 5;
    int lane = tid & 31;
    float b0 = b[lane];
    float b1 = b[lane + 32];
    const float2* __restrict__ h2 = reinterpret_cast<const float2*>(h);

    int gw = blockIdx.x * WPB + warp;
    int nwarps = gridDim.x * WPB;
    const int ngroups = (N_NODES + GPW - 1) / GPW;   // 12500

    for (int g = gw; g < ngroups; g += nwarps) {
        int n0 = g * GPW;

        // ---- phase A: gather ----
        #pragma unroll
        for (int u = 0; u < GPW; u++) {
            int n = n0 + u;
            if (n >= N_NODES) break;
            int beg = g_start[n];
            int cnt = g_count[n];
            float ax = 0.f, ay = 0.f;
            int j = 0;
            for (; j + 3 < cnt; j += 4) {
                EdgeRec e0 = g_edge[beg + j];
                EdgeRec e1 = g_edge[beg + j + 1];
                EdgeRec e2 = g_edge[beg + j + 2];
                EdgeRec e3 = g_edge[beg + j + 3];
                float2 h0 = h2[(size_t)e0.s * 32 + lane];
                float2 h1 = h2[(size_t)e1.s * 32 + lane];
                float2 h2v = h2[(size_t)e2.s * 32 + lane];
                float2 h3 = h2[(size_t)e3.s * 32 + lane];
                ax += h0.x * e0.w + h1.x * e1.w + h2v.x * e2.w + h3.x * e3.w;
                ay += h0.y * e0.w + h1.y * e1.w + h2v.y * e2.w + h3.y * e3.w;
            }
            for (; j < cnt; j++) {
                EdgeRec e0 = g_edge[beg + j];
                float2 h0 = h2[(size_t)e0.s * 32 + lane];
                ax += h0.x * e0.w;
                ay += h0.y * e0.w;
            }
            float inv = 1.0f / fmaxf((float)cnt, 1.0f);
            float2* row2 = reinterpret_cast<float2*>(&hsh4[warp][u][0]);
            row2[lane]      = h2[(size_t)n * 32 + lane];          // h part
            row2[32 + lane] = make_float2(ax * inv, ay * inv);    // h_N part
        }
        __syncwarp();

        // ---- phase B: matvec ----
        float acc0[GPW], acc1[GPW];
        #pragma unroll
        for (int u = 0; u < GPW; u++) { acc0[u] = b0; acc1[u] = b1; }

        #pragma unroll 4
        for (int kq = 0; kq < D2 / 4; kq++) {
            float2 w0 = Wp[(4 * kq + 0) * 33 + lane];
            float2 w1 = Wp[(4 * kq + 1) * 33 + lane];
            float2 w2 = Wp[(4 * kq + 2) * 33 + lane];
            float2 w3 = Wp[(4 * kq + 3) * 33 + lane];
            #pragma unroll
            for (int u = 0; u < GPW; u++) {
                float4 hv = hsh4[warp][u][kq];   // broadcast LDS.128
                acc0[u] += hv.x * w0.x + hv.y * w1.x + hv.z * w2.x + hv.w * w3.x;
                acc1[u] += hv.x * w0.y + hv.y * w1.y + hv.z * w2.y + hv.w * w3.y;
            }
        }

        #pragma unroll
        for (int u = 0; u < GPW; u++) {
            int n = n0 + u;
            if (n >= N_NODES) break;
            out[(size_t)n * D + lane]      = acc0[u];
            out[(size_t)n * D + lane + 32] = acc1[u];
        }
        __syncwarp();   // protect hsh before next iteration overwrites
    }
}

// ---------------------------------------------------------------------------
// Launch
// ---------------------------------------------------------------------------
extern "C" void kernel_launch(void* const* d_in, const int* in_sizes, int n_in,
                              void* d_out, int out_size) {
    const float* h   = (const float*)d_in[0];   // [50000, 64]
    const float* w   = (const float*)d_in[1];   // [800000]
    const int*   src = (const int*)  d_in[2];   // [800000]
    const int*   dst = (const int*)  d_in[3];   // [800000]
    const float* W   = (const float*)d_in[4];   // [64, 128]
    const float* b   = (const float*)d_in[5];   // [64]
    float* out = (float*)d_out;                 // [50000, 64]

    (void)in_sizes; (void)n_in; (void)out_size;

    zero_count_kernel<<<(N_NODES + 255) / 256, 256>>>();
    hist_kernel<<<(N_EDGES / 4 + 255) / 256, 256>>>(dst);
    scanA_kernel<<<NBLK_SCAN, SCAN_BLK>>>();
    scanC_kernel<<<(N_NODES + 255) / 256, 256>>>();
    pos_kernel<<<(N_EDGES / 4 + 255) / 256, 256>>>(src, dst, w);
    fused_kernel<<<592, TPB>>>(h, W, b, out);
}